// round 1
// baseline (speedup 1.0000x reference)
#include <cuda_runtime.h>
#include <cstdint>
#include <cstddef>

#define HH 96
#define WW 96
#define LL 9216          // 96*96
#define NB 8             // batch
#define SCALE_F 0.17677669529663687f   // 1/sqrt(32)

// ---------------- scratch (static device globals; no allocation) ----------------
__device__ float g_bufA[(size_t)NB * 128 * LL];          // 37.75 MB
__device__ float g_bufB[(size_t)NB * 128 * LL];          // 37.75 MB
__device__ float g_LG  [(size_t)NB * 324 * LL];          // 95.6 MB  (attn logits/probs, [b][324][L])
__device__ float g_XW  [(size_t)NB * 4 * 9 * 32 * LL];   // 339.7 MB (xw, [b][h][p][d][L])

// ---------------- generic tiled SGEMM: C[b][m][l] = sum_k W[m][k] * X(k,l) ----------------
// CONV=true : X(k,l) gathers 3x3 conv patches from X[b][k/9][y+ki-1][x+kj-1]
// CONV=false: X(k,l) = X[b][k][l]
// EPI=0 (CBR): out = relu(acc * (g[m]*rsqrt(1+eps)) + b[m]);  EPI=1: out = acc + b[m]
constexpr int BM = 128, BN = 128, BK = 8;

template<bool CONV, int EPI>
__global__ __launch_bounds__(256, 2)
void gemm_k(const float* __restrict__ Wm, const float* __restrict__ X,
            const float* __restrict__ gvec, const float* __restrict__ bvec,
            float* __restrict__ out, int M, int Ktot)
{
    __shared__ float As[BK][BM + 4];   // transposed A, padded vs bank conflicts
    __shared__ float Bs[BK][BN];

    const int tid = threadIdx.x;
    const int b   = blockIdx.z;
    const int m0  = blockIdx.y * BM;
    const int l0  = blockIdx.x * BN;

    const int cin = CONV ? (Ktot / 9) : Ktot;
    const float* Xb = X + (size_t)b * cin * LL;

    // A loader: thread -> (m row, 4 consecutive k)
    const int am   = tid >> 1;
    const int ak   = (tid & 1) << 2;
    const int gm_a = m0 + am;

    // B loader: thread -> (k row, 4 consecutive l)
    const int bk = tid >> 5;
    const int bn = (tid & 31) << 2;
    int yj[4], xj[4];
    #pragma unroll
    for (int j = 0; j < 4; j++) {
        int l = l0 + bn + j;
        yj[j] = l / WW;
        xj[j] = l - yj[j] * WW;
    }

    const int tx = tid & 15;
    const int ty = tid >> 4;

    float acc[8][8];
    #pragma unroll
    for (int i = 0; i < 8; i++)
        #pragma unroll
        for (int j = 0; j < 8; j++) acc[i][j] = 0.f;

    for (int k0 = 0; k0 < Ktot; k0 += BK) {
        // ---- stage A tile (transposed) ----
        float4 a4 = make_float4(0.f, 0.f, 0.f, 0.f);
        if (gm_a < M)
            a4 = *reinterpret_cast<const float4*>(Wm + (size_t)gm_a * Ktot + k0 + ak);
        As[ak + 0][am] = a4.x; As[ak + 1][am] = a4.y;
        As[ak + 2][am] = a4.z; As[ak + 3][am] = a4.w;

        // ---- stage B tile ----
        if (CONV) {
            int k  = k0 + bk;
            int ci = k / 9;
            int rem = k - ci * 9;
            int ki = rem / 3;
            int kj = rem - ki * 3;
            const float* src = Xb + (size_t)ci * LL;
            #pragma unroll
            for (int j = 0; j < 4; j++) {
                int yy = yj[j] + ki - 1;
                int xx = xj[j] + kj - 1;
                float v = 0.f;
                if (yy >= 0 && yy < HH && xx >= 0 && xx < WW)
                    v = src[yy * WW + xx];
                Bs[bk][bn + j] = v;
            }
        } else {
            float4 b4 = *reinterpret_cast<const float4*>(Xb + (size_t)(k0 + bk) * LL + l0 + bn);
            Bs[bk][bn + 0] = b4.x; Bs[bk][bn + 1] = b4.y;
            Bs[bk][bn + 2] = b4.z; Bs[bk][bn + 3] = b4.w;
        }
        __syncthreads();

        // ---- 8x8 register micro-tile FMAs ----
        #pragma unroll
        for (int kk = 0; kk < BK; kk++) {
            float ar[8];
            #pragma unroll
            for (int i = 0; i < 8; i++) ar[i] = As[kk][ty * 8 + i];
            float4 b0 = *reinterpret_cast<const float4*>(&Bs[kk][tx * 8]);
            float4 b1 = *reinterpret_cast<const float4*>(&Bs[kk][tx * 8 + 4]);
            float br[8] = {b0.x, b0.y, b0.z, b0.w, b1.x, b1.y, b1.z, b1.w};
            #pragma unroll
            for (int i = 0; i < 8; i++)
                #pragma unroll
                for (int j = 0; j < 8; j++)
                    acc[i][j] = fmaf(ar[i], br[j], acc[i][j]);
        }
        __syncthreads();
    }

    // ---- epilogue ----
    #pragma unroll
    for (int i = 0; i < 8; i++) {
        int gm = m0 + ty * 8 + i;
        if (gm >= M) continue;
        float bi = bvec[gm];
        float sc = 1.f;
        if (EPI == 0) sc = gvec[gm] * rsqrtf(1.f + 1e-5f);
        float r[8];
        #pragma unroll
        for (int j = 0; j < 8; j++) {
            if (EPI == 0) r[j] = fmaxf(fmaf(acc[i][j], sc, bi), 0.f);
            else          r[j] = acc[i][j] + bi;
        }
        float* orow = out + ((size_t)b * M + gm) * LL + l0 + tx * 8;
        *reinterpret_cast<float4*>(orow)     = make_float4(r[0], r[1], r[2], r[3]);
        *reinterpret_cast<float4*>(orow + 4) = make_float4(r[4], r[5], r[6], r[7]);
    }
}

// ---------------- fused softmax + neighborhood-attention einsum ----------------
// LG[b][h*81 + p*9 + q][l] (raw logits in), V[b][c][l],
// XW[b][h][p][d][l] = sum_q softmax_q(SCALE * LG[b,h,p,:,l]) * V[b, h*32+d, nbr_q(l)]
__global__ __launch_bounds__(256)
void attn_xw_kernel(const float* __restrict__ LG, const float* __restrict__ V,
                    float* __restrict__ XW)
{
    const int tile = blockIdx.x;          // 96 rows * 3 x-tiles
    const int y  = tile / 3;
    const int x0 = (tile % 3) * 32;
    const int h  = blockIdx.y;
    const int b  = blockIdx.z;
    const int tid = threadIdx.x;

    __shared__ float att[32][81];         // per x-lane: 81 logits -> probs (stride 81: conflict-free)
    __shared__ float vsm[3][32][34];      // [qi][d][x0-1 .. x0+32]

    // load logits tile (coalesced over l)
    const float* lgbase = LG + ((size_t)b * 324 + h * 81) * LL + y * WW + x0;
    const int xl = tid & 31;
    for (int idx = tid >> 5; idx < 81; idx += 8)
        att[xl][idx] = lgbase[(size_t)idx * LL + xl];

    // load v 3-row neighborhood for this head
    const float* vbase = V + ((size_t)b * 128 + h * 32) * LL;
    for (int e = tid; e < 3 * 32 * 34; e += 256) {
        int col = e % 34;
        int t2  = e / 34;
        int d   = t2 % 32;
        int qi  = t2 / 32;
        int yy  = y + qi - 1;
        int xx  = x0 + col - 1;
        float val = 0.f;
        if (yy >= 0 && yy < HH && xx >= 0 && xx < WW)
            val = vbase[(size_t)d * LL + yy * WW + xx];
        vsm[qi][d][col] = val;
    }
    __syncthreads();

    // softmax over q for each (x, p) row (288 rows)
    for (int r = tid; r < 288; r += 256) {
        int rx = r / 9, p = r % 9;
        float* row = &att[rx][p * 9];
        float mx = row[0];
        #pragma unroll
        for (int q = 1; q < 9; q++) mx = fmaxf(mx, row[q]);
        float e9[9], s = 0.f;
        #pragma unroll
        for (int q = 0; q < 9; q++) { e9[q] = __expf((row[q] - mx) * SCALE_F); s += e9[q]; }
        float inv = 1.f / s;
        #pragma unroll
        for (int q = 0; q < 9; q++) row[q] = e9[q] * inv;
    }
    __syncthreads();

    // xw[p][d][x] = sum_q att[x][p*9+q] * vsm[q/3][d][x + q%3]
    const int dg = tid >> 5;
    float* xwbase = XW + ((size_t)(b * 4 + h) * 288) * LL + y * WW + x0 + xl;
    #pragma unroll
    for (int p = 0; p < 9; p++) {
        float a[9];
        #pragma unroll
        for (int q = 0; q < 9; q++) a[q] = att[xl][p * 9 + q];
        #pragma unroll
        for (int dd = 0; dd < 4; dd++) {
            int d = dg + dd * 8;
            float s = 0.f;
            #pragma unroll
            for (int q = 0; q < 9; q++)
                s = fmaf(a[q], vsm[q / 3][d][xl + (q % 3)], s);
            xwbase[(size_t)(p * 32 + d) * LL] = s;
        }
    }
}

// ---------------- fold (transpose-of-unfold): 9-tap gather-add ----------------
// F[b][c][y][x] = sum_{ki,kj} XW[b][h][ki*3+kj][d][(y+1-ki)*96 + (x+1-kj)]  (in-bounds)
__global__ void fold_kernel(const float* __restrict__ XW, float* __restrict__ F)
{
    size_t i = (size_t)blockIdx.x * 256 + threadIdx.x;   // exactly 8*128*9216 threads
    int x = (int)(i % WW);
    int y = (int)((i / WW) % HH);
    int c = (int)((i / LL) % 128);
    int b = (int)(i / ((size_t)LL * 128));
    int h = c >> 5, d = c & 31;

    const float* base = XW + ((size_t)(b * 4 + h) * 288 + d) * LL;
    float s = 0.f;
    #pragma unroll
    for (int ki = 0; ki < 3; ki++) {
        int yy = y + 1 - ki;
        if (yy < 0 || yy >= HH) continue;
        #pragma unroll
        for (int kj = 0; kj < 3; kj++) {
            int xx = x + 1 - kj;
            if (xx < 0 || xx >= WW) continue;
            int p = ki * 3 + kj;
            s += base[(size_t)(p * 32) * LL + yy * WW + xx];
        }
    }
    F[i] = s;
}

// ---------------- launch ----------------
extern "C" void kernel_launch(void* const* d_in, const int* in_sizes, int n_in,
                              void* d_out, int out_size)
{
    const float* x       = (const float*)d_in[0];
    const float* fg      = (const float*)d_in[1];
    const float* conv1_w = (const float*)d_in[2];
    const float* bn1_g   = (const float*)d_in[3];
    const float* bn1_b   = (const float*)d_in[4];
    const float* conv2_w = (const float*)d_in[5];
    const float* bn2_g   = (const float*)d_in[6];
    const float* bn2_b   = (const float*)d_in[7];
    const float* v_w     = (const float*)d_in[8];
    const float* v_b     = (const float*)d_in[9];
    const float* attn_w  = (const float*)d_in[10];
    const float* attn_b  = (const float*)d_in[11];
    const float* proj_w  = (const float*)d_in[12];
    const float* proj_b  = (const float*)d_in[13];
    const float* conv3_w = (const float*)d_in[14];
    const float* bn3_g   = (const float*)d_in[15];
    const float* bn3_b   = (const float*)d_in[16];
    const float* conv4_w = (const float*)d_in[17];
    const float* bn4_g   = (const float*)d_in[18];
    const float* bn4_b   = (const float*)d_in[19];
    float* out = (float*)d_out;

    float *bufA, *bufB, *lg, *xw;
    cudaGetSymbolAddress((void**)&bufA, g_bufA);
    cudaGetSymbolAddress((void**)&bufB, g_bufB);
    cudaGetSymbolAddress((void**)&lg,   g_LG);
    cudaGetSymbolAddress((void**)&xw,   g_XW);

    dim3 blk(256);
    dim3 g1(LL / BN, 1, NB);     // M=128 GEMMs
    dim3 g3(LL / BN, 3, NB);     // M=324 GEMM

    // conv1 (64->128) CBR, conv2 (128->128) CBR
    gemm_k<true, 0><<<g1, blk>>>(conv1_w, x,    bn1_g, bn1_b, bufA, 128, 576);
    gemm_k<true, 0><<<g1, blk>>>(conv2_w, bufA, bn2_g, bn2_b, bufB, 128, 1152);
    // v = 1x1 linear
    gemm_k<false, 1><<<g1, blk>>>(v_w, bufB, nullptr, v_b, bufA, 128, 128);
    // attn logits [b][324][L]
    gemm_k<false, 1><<<g3, blk>>>(attn_w, fg, nullptr, attn_b, lg, 324, 128);
    // fused softmax + einsum -> XW
    attn_xw_kernel<<<dim3(HH * 3, 4, NB), blk>>>(lg, bufA, xw);
    // fold -> bufB
    fold_kernel<<<(unsigned)((size_t)NB * 128 * LL / 256), blk>>>(xw, bufB);
    // proj 1x1
    gemm_k<false, 1><<<g1, blk>>>(proj_w, bufB, nullptr, proj_b, bufA, 128, 128);
    // conv3, conv4 CBR (conv4 writes final output)
    gemm_k<true, 0><<<g1, blk>>>(conv3_w, bufA, bn3_g, bn3_b, bufB, 128, 1152);
    gemm_k<true, 0><<<g1, blk>>>(conv4_w, bufB, bn4_g, bn4_b, out, 128, 1152);
}